// round 14
// baseline (speedup 1.0000x reference)
#include <cuda_runtime.h>
#include <math.h>

#define Nn 2048
#define Mm 128
#define Hh 128
#define INF 256
#define NTILES 32   // n-tiles in down pass (64 n each)
#define CN 32       // n chunk staged in smem per k_down block
#define UPSPLIT 8   // m-splits in up pass

// ---------------- scratch (device globals; no allocation allowed) ----------
__device__ float4 g_g4[Nn * Hh];                // packed {g0,g1,g2,pad} per (n,w)
__device__ float g_pair[(size_t)Nn * Mm * 12];  // per pair: x2, sh1(3), sh2(5), pad3
__device__ float g_part[(size_t)NTILES * Mm * Hh * 9]; // partial coarse [nt][m][u][jj]
__device__ float g_coarse[Mm * Hh * 9];         // reduced coarse [m][u][jj]
__device__ float g_cw[Mm * 9 * Hh];             // [m][jj][w]
__device__ float g_up[UPSPLIT * Nn * Hh];       // up-pass partials [ms][n][w]

__device__ __forceinline__ float silu_f(float x) { return x / (1.f + __expf(-x)); }

__device__ __forceinline__ float ex2_fast(float x) {
    float r;
    asm("ex2.approx.ftz.f32 %0, %1;" : "=f"(r) : "f"(x));
    return r;
}

// ---------------- pair table: x2 + real spherical harmonics (lmax=2) -------
// launched twice (half each) so k_down lands in the ncu capture slot (#4)
__global__ void k_pair(const float* __restrict__ gc, const float* __restrict__ cc,
                       int base) {
    int p = base + blockIdx.x * 256 + threadIdx.x;
    if (p >= Nn * Mm) return;
    int n = p >> 7, m = p & 127;
    float dx = gc[n * 3 + 0] - cc[m * 3 + 0];
    float dy = gc[n * 3 + 1] - cc[m * 3 + 1];
    float dz = gc[n * 3 + 2] - cc[m * 3 + 2];
    float x2 = dx * dx + dy * dy + dz * dz + 1e-20f;
    float inv = rsqrtf(x2);
    float x = dx * inv, y = dy * inv, z = dz * inv;
    const float s3 = 1.7320508075688772f;
    float4 A = make_float4(x2, x, y, z);
    float4 B = make_float4(s3 * x * z, s3 * x * y,
                           y * y - 0.5f * (x * x + z * z), s3 * y * z);
    float4 C = make_float4(0.5f * s3 * (z * z - x * x), 0.f, 0.f, 0.f);
    float4* o = reinterpret_cast<float4*>(g_pair + (size_t)p * 12);
    o[0] = A; o[1] = B; o[2] = C;
}

// ---------------- fused: hs = silu(h@Wpre+b); g4 = packed (hs@Wd[l])*gw/norm
// grid Nn/16, block 256
__global__ void k_front(const float* __restrict__ h, const float* __restrict__ Wp,
                        const float* __restrict__ bp, const float* __restrict__ Wd,
                        const float* __restrict__ gw) {
    __shared__ float sA[16 * INF];   // 16KB
    __shared__ float sH[16 * Hh];    // 8KB
    int n0 = blockIdx.x * 16;
    int tid = threadIdx.x;
    for (int i = tid; i < 16 * INF; i += 256) sA[i] = h[n0 * INF + i];
    __syncthreads();
    int w = tid & 127, half = tid >> 7;
    float bb = bp[w];
    float acc[8];
#pragma unroll
    for (int j = 0; j < 8; j++) acc[j] = bb;
    for (int u = 0; u < INF; u++) {
        float wv = Wp[u * Hh + w];
#pragma unroll
        for (int j = 0; j < 8; j++) acc[j] += sA[(half * 8 + j) * INF + u] * wv;
    }
#pragma unroll
    for (int j = 0; j < 8; j++)
        sH[(half * 8 + j) * Hh + w] = silu_f(acc[j]);
    __syncthreads();

    float* g4f = reinterpret_cast<float*>(g_g4);
#pragma unroll
    for (int l = 0; l < 3; l++) {
        float a2[8];
#pragma unroll
        for (int j = 0; j < 8; j++) a2[j] = 0.f;
        const float* W = Wd + l * Hh * Hh;
        for (int u = 0; u < Hh; u++) {
            float wv = W[u * Hh + w];
#pragma unroll
            for (int j = 0; j < 8; j++) a2[j] += sH[(half * 8 + j) * Hh + u] * wv;
        }
        float invn = (l == 0) ? 1.f : ((l == 1) ? 0.5773502691896258f : 0.4472135954999579f);
#pragma unroll
        for (int j = 0; j < 8; j++) {
            int n = n0 + half * 8 + j;
            g4f[((size_t)n * Hh + w) * 4 + l] = a2[j] * gw[n] * invn;
        }
    }
}

// ---------------- down pass: partial coarse per n-tile ---------------------
// grid (Mm/4, NTILES), block 256: thread = (mh, w), each thread handles 2 m
__global__ void __launch_bounds__(256, 5) k_down() {
    int tid = threadIdx.x;
    int w = tid & 127;
    int mh = tid >> 7;             // 0/1: which m-pair within the 4-m block tile
    int m0 = blockIdx.x * 4;
    int nt = blockIdx.y;
    int n0 = nt * (Nn / NTILES);   // 64 n per tile

    __shared__ float4 sp[CN * 12]; // 32 n x (4 m x 12 floats) = 6KB

    // radial basis constants for channel w
    const float MIN_S = 0.32f * 1.88973f * 0.5f;
    const float MAX_S = 2.32f * 1.88973f * 0.5f;
    float s = MIN_S + (MAX_S - MIN_S) * ((float)w / 127.f);
    float temps = 2.f * s * s;
    float a = 1.f / temps;
    float kcoef = -a * 1.4426950408889634f;          // exp(-a x2) = exp2(kcoef*x2)
    float pt = 3.14159265358979323846f * temps;
    float cradw = (2.f / 3.f) * a / (pt * sqrtf(pt)); // w-only factor, applied at end

    float acc[2][9];
#pragma unroll
    for (int mt = 0; mt < 2; mt++)
#pragma unroll
        for (int jj = 0; jj < 9; jj++) acc[mt][jj] = 0.f;

    const float4* pair4 = reinterpret_cast<const float4*>(g_pair);
    const float4* gp = g_g4 + (size_t)n0 * Hh + w;

    for (int c = 0; c < (Nn / NTILES) / CN; c++) {
        int nb = n0 + c * CN;
        __syncthreads();
#pragma unroll
        for (int t = tid; t < CN * 12; t += 256) {
            int ni = t / 12, f = t - ni * 12;
            sp[t] = pair4[(size_t)((nb + ni) * Mm + m0) * 3 + f];
        }
        __syncthreads();

        for (int i = 0; i < CN; i++) {
            float4 gv = gp[(c * CN + i) * Hh];
#pragma unroll
            for (int mt = 0; mt < 2; mt++) {
                const float4* sb = &sp[i * 12 + (mh * 2 + mt) * 3];
                float4 A = sb[0];
                float x2 = A.x;
                float e = ex2_fast(kcoef * x2);
                float r = e * x2;
                float t1 = gv.y * r;
                acc[mt][0] += gv.x * r;           // sh0 == 1
                acc[mt][1] += t1 * A.y;
                acc[mt][2] += t1 * A.z;
                acc[mt][3] += t1 * A.w;
                float t2 = gv.z * r;
                float4 B = sb[1];
                acc[mt][4] += t2 * B.x;
                acc[mt][5] += t2 * B.y;
                acc[mt][6] += t2 * B.z;
                acc[mt][7] += t2 * B.w;
                acc[mt][8] += t2 * sb[2].x;
            }
        }
    }
#pragma unroll
    for (int mt = 0; mt < 2; mt++)
#pragma unroll
        for (int jj = 0; jj < 9; jj++)
            g_part[(((size_t)nt * Mm + (m0 + mh * 2 + mt)) * Hh + w) * 9 + jj] =
                acc[mt][jj] * cradw;
}

// ---------------- reduce partials: g_coarse = sum_nt g_part[nt] ------------
// grid 576, block 256: one thread per (m,u,jj) element, MLP=32
__global__ void __launch_bounds__(256) k_red() {
    int idx = blockIdx.x * 256 + threadIdx.x;   // 0 .. 147455
    const int SZ = Mm * Hh * 9;
    if (idx >= SZ) return;
    float v = 0.f;
#pragma unroll
    for (int nt = 0; nt < NTILES; nt++)
        v += g_part[(size_t)nt * SZ + idx];
    g_coarse[idx] = v;
}

// ---------------- cw[m][jj][w] = (1/norm_l) sum_u coarse[m][u][jj] Wup[l][u][w]
// grid Mm, block 128 (thread = w)
__global__ void __launch_bounds__(128) k_cw(const float* __restrict__ Wu) {
    __shared__ float sc[Hh * 9];
    int m = blockIdx.x;
    int w = threadIdx.x;
    {
        const float4* src = reinterpret_cast<const float4*>(g_coarse + m * Hh * 9);
        float4* dst = reinterpret_cast<float4*>(sc);
        for (int i = w; i < Hh * 9 / 4; i += 128) dst[i] = src[i];
    }
    __syncthreads();
    float acc[9];
#pragma unroll
    for (int jj = 0; jj < 9; jj++) acc[jj] = 0.f;
    for (int u = 0; u < Hh; u++) {
        float w0 = Wu[((0 * Hh + u) * Hh) + w];
        float w1 = Wu[((1 * Hh + u) * Hh) + w];
        float w2 = Wu[((2 * Hh + u) * Hh) + w];
        const float* sv = sc + u * 9;
        acc[0] += sv[0] * w0;
        acc[1] += sv[1] * w1;
        acc[2] += sv[2] * w1;
        acc[3] += sv[3] * w1;
        acc[4] += sv[4] * w2;
        acc[5] += sv[5] * w2;
        acc[6] += sv[6] * w2;
        acc[7] += sv[7] * w2;
        acc[8] += sv[8] * w2;
    }
    const float i1 = 0.5773502691896258f, i2 = 0.4472135954999579f;
    g_cw[(m * 9 + 0) * Hh + w] = acc[0];
    g_cw[(m * 9 + 1) * Hh + w] = acc[1] * i1;
    g_cw[(m * 9 + 2) * Hh + w] = acc[2] * i1;
    g_cw[(m * 9 + 3) * Hh + w] = acc[3] * i1;
    g_cw[(m * 9 + 4) * Hh + w] = acc[4] * i2;
    g_cw[(m * 9 + 5) * Hh + w] = acc[5] * i2;
    g_cw[(m * 9 + 6) * Hh + w] = acc[6] * i2;
    g_cw[(m * 9 + 7) * Hh + w] = acc[7] * i2;
    g_cw[(m * 9 + 8) * Hh + w] = acc[8] * i2;
}

// ---------------- up pass (register-tiled GEMM over k=(m,jj)) --------------
// C[n,w] = sum_{m,jj} sh[n,m,jj] * cw[m,jj,w]
// grid (Nn/16, UPSPLIT): 16 n per block, each y-block handles 16 m (partials).
// block 128 threads: tn = tid>>5 (4 n-groups of 4n), tw = tid&31 (4w each).
#define UPMC 4
__global__ void __launch_bounds__(128) k_up() {
    __shared__ float s_cw[UPMC * 9 * Hh];        // 18KB
    __shared__ float s_prT[UPMC][9][16];         // transposed sh: [mi][jj][ni], 2.25KB
    int tid = threadIdx.x;
    int tn = tid >> 5;          // 0..3 -> n-subtile
    int tw = tid & 31;          // 0..31 -> w-subtile (4 w)
    int n0 = blockIdx.x * 16;
    int ms = blockIdx.y;        // m-split
    const float4* pair4 = reinterpret_cast<const float4*>(g_pair);

    float acc[4][4];
#pragma unroll
    for (int i = 0; i < 4; i++)
#pragma unroll
        for (int j = 0; j < 4; j++) acc[i][j] = 0.f;

    const int MPB = Mm / UPSPLIT;   // 16 m per block
    for (int mc = ms * MPB; mc < ms * MPB + MPB; mc += UPMC) {
        __syncthreads();
        // stage cw chunk (contiguous): UPMC*9*128 floats = 1152 float4
        {
            const float4* src = reinterpret_cast<const float4*>(g_cw + mc * 9 * Hh);
            float4* dst = reinterpret_cast<float4*>(s_cw);
#pragma unroll
            for (int t = tid; t < UPMC * 9 * Hh / 4; t += 128) dst[t] = src[t];
        }
        // stage pair chunk transposed: 16n x UPMC m x 3 float4 = 192 float4
#pragma unroll
        for (int t = tid; t < 16 * UPMC * 3; t += 128) {
            int ni = t / (UPMC * 3);
            int r = t - ni * (UPMC * 3);
            int mi = r / 3, f = r - mi * 3;
            float4 v = pair4[(size_t)((n0 + ni) * Mm + (mc + mi)) * 3 + f];
            if (f == 0) {            // A: (x2, x, y, z) -> jj 1,2,3
                s_prT[mi][1][ni] = v.y;
                s_prT[mi][2][ni] = v.z;
                s_prT[mi][3][ni] = v.w;
            } else if (f == 1) {     // B -> jj 4..7
                s_prT[mi][4][ni] = v.x;
                s_prT[mi][5][ni] = v.y;
                s_prT[mi][6][ni] = v.z;
                s_prT[mi][7][ni] = v.w;
            } else {                 // C.x -> jj 8
                s_prT[mi][8][ni] = v.x;
            }
        }
        __syncthreads();

#pragma unroll
        for (int mi = 0; mi < UPMC; mi++) {
            // jj = 0: sh == 1
            {
                float4 bv = *reinterpret_cast<const float4*>(&s_cw[(mi * 9 + 0) * Hh + tw * 4]);
#pragma unroll
                for (int i = 0; i < 4; i++) {
                    acc[i][0] += bv.x; acc[i][1] += bv.y;
                    acc[i][2] += bv.z; acc[i][3] += bv.w;
                }
            }
#pragma unroll
            for (int jj = 1; jj < 9; jj++) {
                float4 av = *reinterpret_cast<const float4*>(&s_prT[mi][jj][tn * 4]);
                float4 bv = *reinterpret_cast<const float4*>(&s_cw[(mi * 9 + jj) * Hh + tw * 4]);
                float aa[4] = {av.x, av.y, av.z, av.w};
                float bb[4] = {bv.x, bv.y, bv.z, bv.w};
#pragma unroll
                for (int i = 0; i < 4; i++)
#pragma unroll
                    for (int j = 0; j < 4; j++) acc[i][j] += aa[i] * bb[j];
            }
        }
    }
#pragma unroll
    for (int i = 0; i < 4; i++) {
        int n = n0 + tn * 4 + i;
        float4 v = make_float4(acc[i][0], acc[i][1], acc[i][2], acc[i][3]);
        *reinterpret_cast<float4*>(&g_up[((size_t)ms * Nn + n) * Hh + tw * 4]) = v;
    }
}

// ---------------- out = silu((sum_ms up[ms]) @ W_post + b_post) ------------
__global__ void k_post(const float* __restrict__ Wp, const float* __restrict__ bp,
                       float* __restrict__ out) {
    __shared__ float sA[16 * Hh];
    int n0 = blockIdx.x * 16;
    int tid = threadIdx.x;  // 256
    for (int i = tid; i < 16 * Hh; i += 256) {
        float v = 0.f;
#pragma unroll
        for (int ms = 0; ms < UPSPLIT; ms++)
            v += g_up[(size_t)ms * Nn * Hh + n0 * Hh + i];
        sA[i] = v;
    }
    __syncthreads();
    int w = tid & 127, half = tid >> 7;
    float bb = bp[w];
    float acc[8];
#pragma unroll
    for (int j = 0; j < 8; j++) acc[j] = bb;
    for (int u = 0; u < Hh; u++) {
        float wv = Wp[u * Hh + w];
#pragma unroll
        for (int j = 0; j < 8; j++) acc[j] += sA[(half * 8 + j) * Hh + u] * wv;
    }
#pragma unroll
    for (int j = 0; j < 8; j++)
        out[(n0 + half * 8 + j) * Hh + w] = silu_f(acc[j]);
}

// ---------------- launch ---------------------------------------------------
extern "C" void kernel_launch(void* const* d_in, const int* in_sizes, int n_in,
                              void* d_out, int out_size) {
    const float* h     = (const float*)d_in[0];  // [2048,256]
    const float* gc    = (const float*)d_in[1];  // [2048,3]
    const float* cc    = (const float*)d_in[2];  // [128,3]
    const float* gw    = (const float*)d_in[3];  // [2048]
    const float* Wpre  = (const float*)d_in[4];  // [256,128]
    const float* bpre  = (const float*)d_in[5];  // [128]
    const float* Wd    = (const float*)d_in[6];  // [3,128,128]
    const float* Wu    = (const float*)d_in[7];  // [3,128,128]
    const float* Wpost = (const float*)d_in[8];  // [128,128]
    const float* bpost = (const float*)d_in[9];  // [128]
    float* out = (float*)d_out;                  // [2048,128]

    const int HALF = Nn * Mm / 2;                // pair split: 2 launches so
    k_pair<<<HALF / 256, 256>>>(gc, cc, 0);      // k_down is the 4th launch
    k_pair<<<HALF / 256, 256>>>(gc, cc, HALF);   // (ncu capture slot)
    k_front<<<Nn / 16, 256>>>(h, Wpre, bpre, Wd, gw);
    k_down<<<dim3(Mm / 4, NTILES), 256>>>();
    k_red<<<(Mm * Hh * 9 + 255) / 256, 256>>>();
    k_cw<<<Mm, 128>>>(Wu);
    k_up<<<dim3(Nn / 16, UPSPLIT), 128>>>();
    k_post<<<Nn / 16, 256>>>(Wpost, bpost, out);
}

// round 15
// speedup vs baseline: 1.1279x; 1.1279x over previous
#include <cuda_runtime.h>
#include <math.h>

#define Nn 2048
#define Mm 128
#define Hh 128
#define INF 256
#define NTILES 32   // n-tiles in down pass (64 n each)
#define CN 32       // n chunk staged in smem per k_down block
#define UPSPLIT 8   // m-splits in up pass

// ---------------- scratch (device globals; no allocation allowed) ----------
__device__ float4 g_g4[Nn * Hh];                // packed {g0,g1,g2,pad} per (n,w)
__device__ float g_pair[(size_t)Nn * Mm * 12];  // per pair: x2, sh1(3), sh2(5), pad3
__device__ float g_part[(size_t)NTILES * Mm * Hh * 9]; // partial coarse [nt][m][u][jj]
__device__ float g_coarse[Mm * Hh * 9];         // reduced coarse [m][u][jj]
__device__ float g_cw[Mm * 9 * Hh];             // [m][jj][w]
__device__ float g_up[UPSPLIT * Nn * Hh];       // up-pass partials [ms][n][w]

__device__ __forceinline__ float silu_f(float x) { return x / (1.f + __expf(-x)); }

__device__ __forceinline__ float ex2_fast(float x) {
    float r;
    asm("ex2.approx.ftz.f32 %0, %1;" : "=f"(r) : "f"(x));
    return r;
}

// ---------------- pair table: x2 + real spherical harmonics (lmax=2) -------
// launched twice (half each) so k_down lands in the ncu capture slot (#4)
__global__ void k_pair(const float* __restrict__ gc, const float* __restrict__ cc,
                       int base) {
    int p = base + blockIdx.x * 256 + threadIdx.x;
    if (p >= Nn * Mm) return;
    int n = p >> 7, m = p & 127;
    float dx = gc[n * 3 + 0] - cc[m * 3 + 0];
    float dy = gc[n * 3 + 1] - cc[m * 3 + 1];
    float dz = gc[n * 3 + 2] - cc[m * 3 + 2];
    float x2 = dx * dx + dy * dy + dz * dz + 1e-20f;
    float inv = rsqrtf(x2);
    float x = dx * inv, y = dy * inv, z = dz * inv;
    const float s3 = 1.7320508075688772f;
    float4 A = make_float4(x2, x, y, z);
    float4 B = make_float4(s3 * x * z, s3 * x * y,
                           y * y - 0.5f * (x * x + z * z), s3 * y * z);
    float4 C = make_float4(0.5f * s3 * (z * z - x * x), 0.f, 0.f, 0.f);
    float4* o = reinterpret_cast<float4*>(g_pair + (size_t)p * 12);
    o[0] = A; o[1] = B; o[2] = C;
}

// ---------------- fused: hs = silu(h@Wpre+b); g4 = packed (hs@Wd[l])*gw/norm
// grid Nn/16, block 256
__global__ void k_front(const float* __restrict__ h, const float* __restrict__ Wp,
                        const float* __restrict__ bp, const float* __restrict__ Wd,
                        const float* __restrict__ gw) {
    __shared__ float sA[16 * INF];   // 16KB
    __shared__ float sH[16 * Hh];    // 8KB
    int n0 = blockIdx.x * 16;
    int tid = threadIdx.x;
    for (int i = tid; i < 16 * INF; i += 256) sA[i] = h[n0 * INF + i];
    __syncthreads();
    int w = tid & 127, half = tid >> 7;
    float bb = bp[w];
    float acc[8];
#pragma unroll
    for (int j = 0; j < 8; j++) acc[j] = bb;
    for (int u = 0; u < INF; u++) {
        float wv = Wp[u * Hh + w];
#pragma unroll
        for (int j = 0; j < 8; j++) acc[j] += sA[(half * 8 + j) * INF + u] * wv;
    }
#pragma unroll
    for (int j = 0; j < 8; j++)
        sH[(half * 8 + j) * Hh + w] = silu_f(acc[j]);
    __syncthreads();

    float* g4f = reinterpret_cast<float*>(g_g4);
#pragma unroll
    for (int l = 0; l < 3; l++) {
        float a2[8];
#pragma unroll
        for (int j = 0; j < 8; j++) a2[j] = 0.f;
        const float* W = Wd + l * Hh * Hh;
        for (int u = 0; u < Hh; u++) {
            float wv = W[u * Hh + w];
#pragma unroll
            for (int j = 0; j < 8; j++) a2[j] += sH[(half * 8 + j) * Hh + u] * wv;
        }
        float invn = (l == 0) ? 1.f : ((l == 1) ? 0.5773502691896258f : 0.4472135954999579f);
#pragma unroll
        for (int j = 0; j < 8; j++) {
            int n = n0 + half * 8 + j;
            g4f[((size_t)n * Hh + w) * 4 + l] = a2[j] * gw[n] * invn;
        }
    }
}

// ---------------- down pass: partial coarse per n-tile ---------------------
// grid (Mm/4, NTILES), block 128 (thread = w), 4 m per thread (ILP-optimal)
__global__ void __launch_bounds__(128, 8) k_down() {
    int w = threadIdx.x;
    int m0 = blockIdx.x * 4;
    int nt = blockIdx.y;
    int n0 = nt * (Nn / NTILES);   // 64 n per tile

    __shared__ float4 sp[CN * 12]; // 32 n x (4 m x 12 floats) = 6KB

    // radial basis constants for channel w
    const float MIN_S = 0.32f * 1.88973f * 0.5f;
    const float MAX_S = 2.32f * 1.88973f * 0.5f;
    float s = MIN_S + (MAX_S - MIN_S) * ((float)w / 127.f);
    float temps = 2.f * s * s;
    float a = 1.f / temps;
    float kcoef = -a * 1.4426950408889634f;          // exp(-a x2) = exp2(kcoef*x2)
    float pt = 3.14159265358979323846f * temps;
    float cradw = (2.f / 3.f) * a / (pt * sqrtf(pt)); // w-only factor, applied at end

    float acc[4][9];
#pragma unroll
    for (int mt = 0; mt < 4; mt++)
#pragma unroll
        for (int jj = 0; jj < 9; jj++) acc[mt][jj] = 0.f;

    const float4* pair4 = reinterpret_cast<const float4*>(g_pair);
    const float4* gp = g_g4 + (size_t)n0 * Hh + w;

    for (int c = 0; c < (Nn / NTILES) / CN; c++) {
        int nb = n0 + c * CN;
        __syncthreads();
#pragma unroll
        for (int t = w; t < CN * 12; t += 128) {
            int ni = t / 12, f = t - ni * 12;
            sp[t] = pair4[(size_t)((nb + ni) * Mm + m0) * 3 + f];
        }
        __syncthreads();

        for (int i = 0; i < CN; i++) {
            float4 gv = gp[(c * CN + i) * Hh];
            float g0 = gv.x, g1 = gv.y, g2 = gv.z;
#pragma unroll
            for (int mt = 0; mt < 4; mt++) {
                float4 A = sp[i * 12 + mt * 3 + 0];
                float4 B = sp[i * 12 + mt * 3 + 1];
                float4 C = sp[i * 12 + mt * 3 + 2];
                float x2 = A.x;
                float e = ex2_fast(kcoef * x2);
                float r = e * x2;
                float t1 = g1 * r, t2 = g2 * r;
                acc[mt][0] += g0 * r;             // sh0 == 1
                acc[mt][1] += t1 * A.y;
                acc[mt][2] += t1 * A.z;
                acc[mt][3] += t1 * A.w;
                acc[mt][4] += t2 * B.x;
                acc[mt][5] += t2 * B.y;
                acc[mt][6] += t2 * B.z;
                acc[mt][7] += t2 * B.w;
                acc[mt][8] += t2 * C.x;
            }
        }
    }
#pragma unroll
    for (int mt = 0; mt < 4; mt++)
#pragma unroll
        for (int jj = 0; jj < 9; jj++)
            g_part[(((size_t)nt * Mm + (m0 + mt)) * Hh + w) * 9 + jj] =
                acc[mt][jj] * cradw;
}

// ---------------- reduce partials: g_coarse = sum_nt g_part[nt] ------------
// grid 576, block 256: one thread per (m,u,jj) element, MLP=32
__global__ void __launch_bounds__(256) k_red() {
    int idx = blockIdx.x * 256 + threadIdx.x;   // 0 .. 147455
    const int SZ = Mm * Hh * 9;
    if (idx >= SZ) return;
    float v = 0.f;
#pragma unroll
    for (int nt = 0; nt < NTILES; nt++)
        v += g_part[(size_t)nt * SZ + idx];
    g_coarse[idx] = v;
}

// ---------------- cw[m][jj][w] = (1/norm_l) sum_u coarse[m][u][jj] Wup[l][u][w]
// grid Mm, block 128 (thread = w)
__global__ void __launch_bounds__(128) k_cw(const float* __restrict__ Wu) {
    __shared__ float sc[Hh * 9];
    int m = blockIdx.x;
    int w = threadIdx.x;
    {
        const float4* src = reinterpret_cast<const float4*>(g_coarse + m * Hh * 9);
        float4* dst = reinterpret_cast<float4*>(sc);
        for (int i = w; i < Hh * 9 / 4; i += 128) dst[i] = src[i];
    }
    __syncthreads();
    float acc[9];
#pragma unroll
    for (int jj = 0; jj < 9; jj++) acc[jj] = 0.f;
    for (int u = 0; u < Hh; u++) {
        float w0 = Wu[((0 * Hh + u) * Hh) + w];
        float w1 = Wu[((1 * Hh + u) * Hh) + w];
        float w2 = Wu[((2 * Hh + u) * Hh) + w];
        const float* sv = sc + u * 9;
        acc[0] += sv[0] * w0;
        acc[1] += sv[1] * w1;
        acc[2] += sv[2] * w1;
        acc[3] += sv[3] * w1;
        acc[4] += sv[4] * w2;
        acc[5] += sv[5] * w2;
        acc[6] += sv[6] * w2;
        acc[7] += sv[7] * w2;
        acc[8] += sv[8] * w2;
    }
    const float i1 = 0.5773502691896258f, i2 = 0.4472135954999579f;
    g_cw[(m * 9 + 0) * Hh + w] = acc[0];
    g_cw[(m * 9 + 1) * Hh + w] = acc[1] * i1;
    g_cw[(m * 9 + 2) * Hh + w] = acc[2] * i1;
    g_cw[(m * 9 + 3) * Hh + w] = acc[3] * i1;
    g_cw[(m * 9 + 4) * Hh + w] = acc[4] * i2;
    g_cw[(m * 9 + 5) * Hh + w] = acc[5] * i2;
    g_cw[(m * 9 + 6) * Hh + w] = acc[6] * i2;
    g_cw[(m * 9 + 7) * Hh + w] = acc[7] * i2;
    g_cw[(m * 9 + 8) * Hh + w] = acc[8] * i2;
}

// ---------------- up pass (register-tiled GEMM over k=(m,jj)) --------------
// C[n,w] = sum_{m,jj} sh[n,m,jj] * cw[m,jj,w]
// grid (Nn/16, UPSPLIT): 16 n per block, each y-block handles 16 m (partials).
// block 128 threads: tn = tid>>5 (4 n-groups of 4n), tw = tid&31 (4w each).
#define UPMC 4
__global__ void __launch_bounds__(128) k_up() {
    __shared__ float s_cw[UPMC * 9 * Hh];        // 18KB
    __shared__ float s_prT[UPMC][9][16];         // transposed sh: [mi][jj][ni], 2.25KB
    int tid = threadIdx.x;
    int tn = tid >> 5;          // 0..3 -> n-subtile
    int tw = tid & 31;          // 0..31 -> w-subtile (4 w)
    int n0 = blockIdx.x * 16;
    int ms = blockIdx.y;        // m-split
    const float4* pair4 = reinterpret_cast<const float4*>(g_pair);

    float acc[4][4];
#pragma unroll
    for (int i = 0; i < 4; i++)
#pragma unroll
        for (int j = 0; j < 4; j++) acc[i][j] = 0.f;

    const int MPB = Mm / UPSPLIT;   // 16 m per block
    for (int mc = ms * MPB; mc < ms * MPB + MPB; mc += UPMC) {
        __syncthreads();
        // stage cw chunk (contiguous): UPMC*9*128 floats = 1152 float4
        {
            const float4* src = reinterpret_cast<const float4*>(g_cw + mc * 9 * Hh);
            float4* dst = reinterpret_cast<float4*>(s_cw);
#pragma unroll
            for (int t = tid; t < UPMC * 9 * Hh / 4; t += 128) dst[t] = src[t];
        }
        // stage pair chunk transposed: 16n x UPMC m x 3 float4 = 192 float4
#pragma unroll
        for (int t = tid; t < 16 * UPMC * 3; t += 128) {
            int ni = t / (UPMC * 3);
            int r = t - ni * (UPMC * 3);
            int mi = r / 3, f = r - mi * 3;
            float4 v = pair4[(size_t)((n0 + ni) * Mm + (mc + mi)) * 3 + f];
            if (f == 0) {            // A: (x2, x, y, z) -> jj 1,2,3
                s_prT[mi][1][ni] = v.y;
                s_prT[mi][2][ni] = v.z;
                s_prT[mi][3][ni] = v.w;
            } else if (f == 1) {     // B -> jj 4..7
                s_prT[mi][4][ni] = v.x;
                s_prT[mi][5][ni] = v.y;
                s_prT[mi][6][ni] = v.z;
                s_prT[mi][7][ni] = v.w;
            } else {                 // C.x -> jj 8
                s_prT[mi][8][ni] = v.x;
            }
        }
        __syncthreads();

#pragma unroll
        for (int mi = 0; mi < UPMC; mi++) {
            // jj = 0: sh == 1
            {
                float4 bv = *reinterpret_cast<const float4*>(&s_cw[(mi * 9 + 0) * Hh + tw * 4]);
#pragma unroll
                for (int i = 0; i < 4; i++) {
                    acc[i][0] += bv.x; acc[i][1] += bv.y;
                    acc[i][2] += bv.z; acc[i][3] += bv.w;
                }
            }
#pragma unroll
            for (int jj = 1; jj < 9; jj++) {
                float4 av = *reinterpret_cast<const float4*>(&s_prT[mi][jj][tn * 4]);
                float4 bv = *reinterpret_cast<const float4*>(&s_cw[(mi * 9 + jj) * Hh + tw * 4]);
                float aa[4] = {av.x, av.y, av.z, av.w};
                float bb[4] = {bv.x, bv.y, bv.z, bv.w};
#pragma unroll
                for (int i = 0; i < 4; i++)
#pragma unroll
                    for (int j = 0; j < 4; j++) acc[i][j] += aa[i] * bb[j];
            }
        }
    }
#pragma unroll
    for (int i = 0; i < 4; i++) {
        int n = n0 + tn * 4 + i;
        float4 v = make_float4(acc[i][0], acc[i][1], acc[i][2], acc[i][3]);
        *reinterpret_cast<float4*>(&g_up[((size_t)ms * Nn + n) * Hh + tw * 4]) = v;
    }
}

// ---------------- out = silu((sum_ms up[ms]) @ W_post + b_post) ------------
__global__ void k_post(const float* __restrict__ Wp, const float* __restrict__ bp,
                       float* __restrict__ out) {
    __shared__ float sA[16 * Hh];
    int n0 = blockIdx.x * 16;
    int tid = threadIdx.x;  // 256
    for (int i = tid; i < 16 * Hh; i += 256) {
        float v = 0.f;
#pragma unroll
        for (int ms = 0; ms < UPSPLIT; ms++)
            v += g_up[(size_t)ms * Nn * Hh + n0 * Hh + i];
        sA[i] = v;
    }
    __syncthreads();
    int w = tid & 127, half = tid >> 7;
    float bb = bp[w];
    float acc[8];
#pragma unroll
    for (int j = 0; j < 8; j++) acc[j] = bb;
    for (int u = 0; u < Hh; u++) {
        float wv = Wp[u * Hh + w];
#pragma unroll
        for (int j = 0; j < 8; j++) acc[j] += sA[(half * 8 + j) * Hh + u] * wv;
    }
#pragma unroll
    for (int j = 0; j < 8; j++)
        out[(n0 + half * 8 + j) * Hh + w] = silu_f(acc[j]);
}

// ---------------- launch ---------------------------------------------------
extern "C" void kernel_launch(void* const* d_in, const int* in_sizes, int n_in,
                              void* d_out, int out_size) {
    const float* h     = (const float*)d_in[0];  // [2048,256]
    const float* gc    = (const float*)d_in[1];  // [2048,3]
    const float* cc    = (const float*)d_in[2];  // [128,3]
    const float* gw    = (const float*)d_in[3];  // [2048]
    const float* Wpre  = (const float*)d_in[4];  // [256,128]
    const float* bpre  = (const float*)d_in[5];  // [128]
    const float* Wd    = (const float*)d_in[6];  // [3,128,128]
    const float* Wu    = (const float*)d_in[7];  // [3,128,128]
    const float* Wpost = (const float*)d_in[8];  // [128,128]
    const float* bpost = (const float*)d_in[9];  // [128]
    float* out = (float*)d_out;                  // [2048,128]

    const int HALF = Nn * Mm / 2;                // pair split: 2 launches so
    k_pair<<<HALF / 256, 256>>>(gc, cc, 0);      // k_down is the 4th launch
    k_pair<<<HALF / 256, 256>>>(gc, cc, HALF);   // (ncu capture slot)
    k_front<<<Nn / 16, 256>>>(h, Wpre, bpre, Wd, gw);
    k_down<<<dim3(Mm / 4, NTILES), 128>>>();
    k_red<<<(Mm * Hh * 9 + 255) / 256, 256>>>();
    k_cw<<<Mm, 128>>>(Wu);
    k_up<<<dim3(Nn / 16, UPSPLIT), 128>>>();
    k_post<<<Nn / 16, 256>>>(Wpost, bpost, out);
}

// round 16
// speedup vs baseline: 1.1282x; 1.0002x over previous
#include <cuda_runtime.h>
#include <math.h>

#define Nn 2048
#define Mm 128
#define Hh 128
#define INF 256
#define NTILES 32   // n-tiles in down pass (64 n each)
#define CN 32       // n chunk staged in smem per k_down block
#define UPSPLIT 8   // m-splits in up pass

// ---------------- scratch (device globals; no allocation allowed) ----------
__device__ float4 g_g4[Nn * Hh];                // packed {g0,g1,g2,pad} per (n,w)
__device__ float g_pair[(size_t)Nn * Mm * 12];  // per pair: x2, sh1(3), sh2(5), pad3
__device__ float g_part[(size_t)NTILES * Mm * Hh * 9]; // partial coarse [nt][m][u][jj]
__device__ float g_coarse[Mm * Hh * 9];         // reduced coarse [m][u][jj]
__device__ float g_cw[Mm * 9 * Hh];             // [m][jj][w]
__device__ float g_up[UPSPLIT * Nn * Hh];       // up-pass partials [ms][n][w]

__device__ __forceinline__ float silu_f(float x) { return x / (1.f + __expf(-x)); }

__device__ __forceinline__ float ex2_fast(float x) {
    float r;
    asm("ex2.approx.ftz.f32 %0, %1;" : "=f"(r) : "f"(x));
    return r;
}

// ---------------- pair table: x2 + real spherical harmonics (lmax=2) -------
// launched twice (half each) so k_down lands in the ncu capture slot (#4)
__global__ void k_pair(const float* __restrict__ gc, const float* __restrict__ cc,
                       int base) {
    int p = base + blockIdx.x * 256 + threadIdx.x;
    if (p >= Nn * Mm) return;
    int n = p >> 7, m = p & 127;
    float dx = gc[n * 3 + 0] - cc[m * 3 + 0];
    float dy = gc[n * 3 + 1] - cc[m * 3 + 1];
    float dz = gc[n * 3 + 2] - cc[m * 3 + 2];
    float x2 = dx * dx + dy * dy + dz * dz + 1e-20f;
    float inv = rsqrtf(x2);
    float x = dx * inv, y = dy * inv, z = dz * inv;
    const float s3 = 1.7320508075688772f;
    float4 A = make_float4(x2, x, y, z);
    float4 B = make_float4(s3 * x * z, s3 * x * y,
                           y * y - 0.5f * (x * x + z * z), s3 * y * z);
    float4 C = make_float4(0.5f * s3 * (z * z - x * x), 0.f, 0.f, 0.f);
    float4* o = reinterpret_cast<float4*>(g_pair + (size_t)p * 12);
    o[0] = A; o[1] = B; o[2] = C;
}

// ---------------- fused: hs = silu(h@Wpre+b); g4 = packed (hs@Wd[l])*gw/norm
// grid Nn/16, block 256
__global__ void k_front(const float* __restrict__ h, const float* __restrict__ Wp,
                        const float* __restrict__ bp, const float* __restrict__ Wd,
                        const float* __restrict__ gw) {
    __shared__ float sA[16 * INF];   // 16KB
    __shared__ float sH[16 * Hh];    // 8KB
    int n0 = blockIdx.x * 16;
    int tid = threadIdx.x;
    for (int i = tid; i < 16 * INF; i += 256) sA[i] = h[n0 * INF + i];
    __syncthreads();
    int w = tid & 127, half = tid >> 7;
    float bb = bp[w];
    float acc[8];
#pragma unroll
    for (int j = 0; j < 8; j++) acc[j] = bb;
    for (int u = 0; u < INF; u++) {
        float wv = Wp[u * Hh + w];
#pragma unroll
        for (int j = 0; j < 8; j++) acc[j] += sA[(half * 8 + j) * INF + u] * wv;
    }
#pragma unroll
    for (int j = 0; j < 8; j++)
        sH[(half * 8 + j) * Hh + w] = silu_f(acc[j]);
    __syncthreads();

    float* g4f = reinterpret_cast<float*>(g_g4);
#pragma unroll
    for (int l = 0; l < 3; l++) {
        float a2[8];
#pragma unroll
        for (int j = 0; j < 8; j++) a2[j] = 0.f;
        const float* W = Wd + l * Hh * Hh;
        for (int u = 0; u < Hh; u++) {
            float wv = W[u * Hh + w];
#pragma unroll
            for (int j = 0; j < 8; j++) a2[j] += sH[(half * 8 + j) * Hh + u] * wv;
        }
        float invn = (l == 0) ? 1.f : ((l == 1) ? 0.5773502691896258f : 0.4472135954999579f);
#pragma unroll
        for (int j = 0; j < 8; j++) {
            int n = n0 + half * 8 + j;
            g4f[((size_t)n * Hh + w) * 4 + l] = a2[j] * gw[n] * invn;
        }
    }
}

// ---------------- down pass: partial coarse per n-tile ---------------------
// grid (Mm/4, NTILES), block 128 (thread = w), 4 m per thread (ILP-optimal)
__global__ void __launch_bounds__(128, 8) k_down() {
    int w = threadIdx.x;
    int m0 = blockIdx.x * 4;
    int nt = blockIdx.y;
    int n0 = nt * (Nn / NTILES);   // 64 n per tile

    __shared__ float4 sp[CN * 12]; // 32 n x (4 m x 12 floats) = 6KB

    // radial basis constants for channel w
    const float MIN_S = 0.32f * 1.88973f * 0.5f;
    const float MAX_S = 2.32f * 1.88973f * 0.5f;
    float s = MIN_S + (MAX_S - MIN_S) * ((float)w / 127.f);
    float temps = 2.f * s * s;
    float a = 1.f / temps;
    float kcoef = -a * 1.4426950408889634f;          // exp(-a x2) = exp2(kcoef*x2)
    float pt = 3.14159265358979323846f * temps;
    float cradw = (2.f / 3.f) * a / (pt * sqrtf(pt)); // w-only factor, applied at end

    float acc[4][9];
#pragma unroll
    for (int mt = 0; mt < 4; mt++)
#pragma unroll
        for (int jj = 0; jj < 9; jj++) acc[mt][jj] = 0.f;

    const float4* pair4 = reinterpret_cast<const float4*>(g_pair);
    const float4* gp = g_g4 + (size_t)n0 * Hh + w;

    for (int c = 0; c < (Nn / NTILES) / CN; c++) {
        int nb = n0 + c * CN;
        __syncthreads();
#pragma unroll
        for (int t = w; t < CN * 12; t += 128) {
            int ni = t / 12, f = t - ni * 12;
            sp[t] = pair4[(size_t)((nb + ni) * Mm + m0) * 3 + f];
        }
        __syncthreads();

        for (int i = 0; i < CN; i++) {
            float4 gv = gp[(c * CN + i) * Hh];
            float g0 = gv.x, g1 = gv.y, g2 = gv.z;
#pragma unroll
            for (int mt = 0; mt < 4; mt++) {
                float4 A = sp[i * 12 + mt * 3 + 0];
                float4 B = sp[i * 12 + mt * 3 + 1];
                float4 C = sp[i * 12 + mt * 3 + 2];
                float x2 = A.x;
                float e = ex2_fast(kcoef * x2);
                float r = e * x2;
                float t1 = g1 * r, t2 = g2 * r;
                acc[mt][0] += g0 * r;             // sh0 == 1
                acc[mt][1] += t1 * A.y;
                acc[mt][2] += t1 * A.z;
                acc[mt][3] += t1 * A.w;
                acc[mt][4] += t2 * B.x;
                acc[mt][5] += t2 * B.y;
                acc[mt][6] += t2 * B.z;
                acc[mt][7] += t2 * B.w;
                acc[mt][8] += t2 * C.x;
            }
        }
    }
#pragma unroll
    for (int mt = 0; mt < 4; mt++)
#pragma unroll
        for (int jj = 0; jj < 9; jj++)
            g_part[(((size_t)nt * Mm + (m0 + mt)) * Hh + w) * 9 + jj] =
                acc[mt][jj] * cradw;
}

// ---------------- reduce partials: g_coarse = sum_nt g_part[nt] ------------
// grid 576, block 256: one thread per (m,u,jj) element, MLP=32
__global__ void __launch_bounds__(256) k_red() {
    int idx = blockIdx.x * 256 + threadIdx.x;   // 0 .. 147455
    const int SZ = Mm * Hh * 9;
    if (idx >= SZ) return;
    float v = 0.f;
#pragma unroll
    for (int nt = 0; nt < NTILES; nt++)
        v += g_part[(size_t)nt * SZ + idx];
    g_coarse[idx] = v;
}

// ---------------- cw[m][jj][w] = (1/norm_l) sum_u coarse[m][u][jj] Wup[l][u][w]
// grid Mm, block 128 (thread = w)
__global__ void __launch_bounds__(128) k_cw(const float* __restrict__ Wu) {
    __shared__ float sc[Hh * 9];
    int m = blockIdx.x;
    int w = threadIdx.x;
    {
        const float4* src = reinterpret_cast<const float4*>(g_coarse + m * Hh * 9);
        float4* dst = reinterpret_cast<float4*>(sc);
        for (int i = w; i < Hh * 9 / 4; i += 128) dst[i] = src[i];
    }
    __syncthreads();
    float acc[9];
#pragma unroll
    for (int jj = 0; jj < 9; jj++) acc[jj] = 0.f;
    for (int u = 0; u < Hh; u++) {
        float w0 = Wu[((0 * Hh + u) * Hh) + w];
        float w1 = Wu[((1 * Hh + u) * Hh) + w];
        float w2 = Wu[((2 * Hh + u) * Hh) + w];
        const float* sv = sc + u * 9;
        acc[0] += sv[0] * w0;
        acc[1] += sv[1] * w1;
        acc[2] += sv[2] * w1;
        acc[3] += sv[3] * w1;
        acc[4] += sv[4] * w2;
        acc[5] += sv[5] * w2;
        acc[6] += sv[6] * w2;
        acc[7] += sv[7] * w2;
        acc[8] += sv[8] * w2;
    }
    const float i1 = 0.5773502691896258f, i2 = 0.4472135954999579f;
    g_cw[(m * 9 + 0) * Hh + w] = acc[0];
    g_cw[(m * 9 + 1) * Hh + w] = acc[1] * i1;
    g_cw[(m * 9 + 2) * Hh + w] = acc[2] * i1;
    g_cw[(m * 9 + 3) * Hh + w] = acc[3] * i1;
    g_cw[(m * 9 + 4) * Hh + w] = acc[4] * i2;
    g_cw[(m * 9 + 5) * Hh + w] = acc[5] * i2;
    g_cw[(m * 9 + 6) * Hh + w] = acc[6] * i2;
    g_cw[(m * 9 + 7) * Hh + w] = acc[7] * i2;
    g_cw[(m * 9 + 8) * Hh + w] = acc[8] * i2;
}

// ---------------- up pass (register-tiled GEMM over k=(m,jj)) --------------
// C[n,w] = sum_{m,jj} sh[n,m,jj] * cw[m,jj,w]
// grid (Nn/16, UPSPLIT): 16 n per block, each y-block handles 16 m (partials).
// block 128 threads: tn = tid>>5 (4 n-groups of 4n), tw = tid&31 (4w each).
#define UPMC 4
__global__ void __launch_bounds__(128) k_up() {
    __shared__ float s_cw[UPMC * 9 * Hh];        // 18KB
    __shared__ float s_prT[UPMC][9][16];         // transposed sh: [mi][jj][ni], 2.25KB
    int tid = threadIdx.x;
    int tn = tid >> 5;          // 0..3 -> n-subtile
    int tw = tid & 31;          // 0..31 -> w-subtile (4 w)
    int n0 = blockIdx.x * 16;
    int ms = blockIdx.y;        // m-split
    const float4* pair4 = reinterpret_cast<const float4*>(g_pair);

    float acc[4][4];
#pragma unroll
    for (int i = 0; i < 4; i++)
#pragma unroll
        for (int j = 0; j < 4; j++) acc[i][j] = 0.f;

    const int MPB = Mm / UPSPLIT;   // 16 m per block
    for (int mc = ms * MPB; mc < ms * MPB + MPB; mc += UPMC) {
        __syncthreads();
        // stage cw chunk (contiguous): UPMC*9*128 floats = 1152 float4
        {
            const float4* src = reinterpret_cast<const float4*>(g_cw + mc * 9 * Hh);
            float4* dst = reinterpret_cast<float4*>(s_cw);
#pragma unroll
            for (int t = tid; t < UPMC * 9 * Hh / 4; t += 128) dst[t] = src[t];
        }
        // stage pair chunk transposed: 16n x UPMC m x 3 float4 = 192 float4
#pragma unroll
        for (int t = tid; t < 16 * UPMC * 3; t += 128) {
            int ni = t / (UPMC * 3);
            int r = t - ni * (UPMC * 3);
            int mi = r / 3, f = r - mi * 3;
            float4 v = pair4[(size_t)((n0 + ni) * Mm + (mc + mi)) * 3 + f];
            if (f == 0) {            // A: (x2, x, y, z) -> jj 1,2,3
                s_prT[mi][1][ni] = v.y;
                s_prT[mi][2][ni] = v.z;
                s_prT[mi][3][ni] = v.w;
            } else if (f == 1) {     // B -> jj 4..7
                s_prT[mi][4][ni] = v.x;
                s_prT[mi][5][ni] = v.y;
                s_prT[mi][6][ni] = v.z;
                s_prT[mi][7][ni] = v.w;
            } else {                 // C.x -> jj 8
                s_prT[mi][8][ni] = v.x;
            }
        }
        __syncthreads();

#pragma unroll
        for (int mi = 0; mi < UPMC; mi++) {
            // jj = 0: sh == 1
            {
                float4 bv = *reinterpret_cast<const float4*>(&s_cw[(mi * 9 + 0) * Hh + tw * 4]);
#pragma unroll
                for (int i = 0; i < 4; i++) {
                    acc[i][0] += bv.x; acc[i][1] += bv.y;
                    acc[i][2] += bv.z; acc[i][3] += bv.w;
                }
            }
#pragma unroll
            for (int jj = 1; jj < 9; jj++) {
                float4 av = *reinterpret_cast<const float4*>(&s_prT[mi][jj][tn * 4]);
                float4 bv = *reinterpret_cast<const float4*>(&s_cw[(mi * 9 + jj) * Hh + tw * 4]);
                float aa[4] = {av.x, av.y, av.z, av.w};
                float bb[4] = {bv.x, bv.y, bv.z, bv.w};
#pragma unroll
                for (int i = 0; i < 4; i++)
#pragma unroll
                    for (int j = 0; j < 4; j++) acc[i][j] += aa[i] * bb[j];
            }
        }
    }
#pragma unroll
    for (int i = 0; i < 4; i++) {
        int n = n0 + tn * 4 + i;
        float4 v = make_float4(acc[i][0], acc[i][1], acc[i][2], acc[i][3]);
        *reinterpret_cast<float4*>(&g_up[((size_t)ms * Nn + n) * Hh + tw * 4]) = v;
    }
}

// ---------------- out = silu((sum_ms up[ms]) @ W_post + b_post) ------------
__global__ void k_post(const float* __restrict__ Wp, const float* __restrict__ bp,
                       float* __restrict__ out) {
    __shared__ float sA[16 * Hh];
    int n0 = blockIdx.x * 16;
    int tid = threadIdx.x;  // 256
    for (int i = tid; i < 16 * Hh; i += 256) {
        float v = 0.f;
#pragma unroll
        for (int ms = 0; ms < UPSPLIT; ms++)
            v += g_up[(size_t)ms * Nn * Hh + n0 * Hh + i];
        sA[i] = v;
    }
    __syncthreads();
    int w = tid & 127, half = tid >> 7;
    float bb = bp[w];
    float acc[8];
#pragma unroll
    for (int j = 0; j < 8; j++) acc[j] = bb;
    for (int u = 0; u < Hh; u++) {
        float wv = Wp[u * Hh + w];
#pragma unroll
        for (int j = 0; j < 8; j++) acc[j] += sA[(half * 8 + j) * Hh + u] * wv;
    }
#pragma unroll
    for (int j = 0; j < 8; j++)
        out[(n0 + half * 8 + j) * Hh + w] = silu_f(acc[j]);
}

// ---------------- launch ---------------------------------------------------
extern "C" void kernel_launch(void* const* d_in, const int* in_sizes, int n_in,
                              void* d_out, int out_size) {
    const float* h     = (const float*)d_in[0];  // [2048,256]
    const float* gc    = (const float*)d_in[1];  // [2048,3]
    const float* cc    = (const float*)d_in[2];  // [128,3]
    const float* gw    = (const float*)d_in[3];  // [2048]
    const float* Wpre  = (const float*)d_in[4];  // [256,128]
    const float* bpre  = (const float*)d_in[5];  // [128]
    const float* Wd    = (const float*)d_in[6];  // [3,128,128]
    const float* Wu    = (const float*)d_in[7];  // [3,128,128]
    const float* Wpost = (const float*)d_in[8];  // [128,128]
    const float* bpost = (const float*)d_in[9];  // [128]
    float* out = (float*)d_out;                  // [2048,128]

    const int HALF = Nn * Mm / 2;                // pair split: 2 launches so
    k_pair<<<HALF / 256, 256>>>(gc, cc, 0);      // k_down is the 4th launch
    k_pair<<<HALF / 256, 256>>>(gc, cc, HALF);   // (ncu capture slot)
    k_front<<<Nn / 16, 256>>>(h, Wpre, bpre, Wd, gw);
    k_down<<<dim3(Mm / 4, NTILES), 128>>>();
    k_red<<<(Mm * Hh * 9 + 255) / 256, 256>>>();
    k_cw<<<Mm, 128>>>(Wu);
    k_up<<<dim3(Nn / 16, UPSPLIT), 128>>>();
    k_post<<<Nn / 16, 256>>>(Wpost, bpost, out);
}